// round 16
// baseline (speedup 1.0000x reference)
#include <cuda_runtime.h>
#include <mma.h>
#include <math.h>

using namespace nvcuda;

#define NMAX 50000
#define EMAX 800000
#define SEG_CAP 2560   // max edges staged per 64-row block (mean ~1024, 48 sigma)

// ---------------- scratch (no allocation allowed) ----------------
__device__ __align__(16) int   g_cnt[NMAX];        // in-degree; re-zeroed by gemm2
__device__ __align__(16) int   g_rp[NMAX];         // CSR row ptr; fill advances it to row END
__device__ int                 g_base;             // slot counter; re-zeroed by gemm2
__device__ __align__(16) float g_dinv[NMAX];
__device__ __align__(16) float g_invrs[NMAX];
__device__ __align__(16) float g_Wt[128 * 64];     // tf32, transformed W1
__device__ __align__(16) float2 g_csr[EMAX + NMAX]; // (src bits, weight); rows even-aligned
__device__ __align__(16) float g_y[4 * NMAX * 16]; // layer-1 projections y_k
__device__ __align__(16) float g_t[NMAX * 16];
__device__ __align__(16) float g_u[NMAX * 16];
__device__ __align__(16) float g_G[4 * NMAX * 16]; // layer-2 hops

// ---------------- CSR build ----------------
__global__ void k_hist(const int* __restrict__ ei, int* __restrict__ cnt, int E) {
  int e = (blockIdx.x * blockDim.x + threadIdx.x) * 2;
  if (e >= E) return;
  atomicAdd(&cnt[ei[E + e]], 1);
  if (e + 1 < E) atomicAdd(&cnt[ei[E + e + 1]], 1);
}

// fused: blocks [0, nW) -> warp-per-row inv_rowsum; block nW -> W1 tf32 transform
__global__ void k_prep(const float* __restrict__ x, float* __restrict__ invrs,
                       const float* __restrict__ W1, float* __restrict__ Wt,
                       int n, int nW) {
  if ((int)blockIdx.x == nW) {
    int tid = threadIdx.x;
    for (int s = tid; s < 8192; s += 256) {
      int d = s >> 6, c = s & 63;
      Wt[s] = wmma::__float_to_tf32(W1[(((c >> 4) << 7) | d) * 16 + (c & 15)]);
    }
    return;
  }
  int w = (blockIdx.x * blockDim.x + threadIdx.x) >> 5;
  int lane = threadIdx.x & 31;
  if (w >= n) return;
  const float4* x4 = (const float4*)x;
  float4 v = x4[w * 32 + lane];
  float s = v.x + v.y + v.z + v.w;
  #pragma unroll
  for (int o = 16; o; o >>= 1) s += __shfl_xor_sync(0xffffffffu, s, o);
  if (lane == 0) invrs[w] = 1.0f / fmaxf(s, 1e-8f);
}

// per-1024-block exclusive scan over EVEN-PADDED lengths + atomic block base.
__global__ __launch_bounds__(1024) void k_scan1(const int* __restrict__ cnt,
                                                int* __restrict__ rp,
                                                int* __restrict__ base,
                                                float* __restrict__ dinv, int n) {
  __shared__ int ws[32];
  __shared__ int blockBase;
  int t = threadIdx.x;
  int i = blockIdx.x * 1024 + t;
  int c = (i < n) ? cnt[i] : 0;
  if (i < n) dinv[i] = (c > 0) ? rsqrtf((float)c) : 0.f;
  int cp = (c + 1) & ~1;          // even-padded allocation
  int s = cp;
  #pragma unroll
  for (int o = 1; o < 32; o <<= 1) {
    int p = __shfl_up_sync(0xffffffffu, s, o);
    if ((t & 31) >= o) s += p;
  }
  if ((t & 31) == 31) ws[t >> 5] = s;
  __syncthreads();
  if (t < 32) {
    int b = ws[t];
    int sb = b;
    #pragma unroll
    for (int o = 1; o < 32; o <<= 1) {
      int p = __shfl_up_sync(0xffffffffu, sb, o);
      if (t >= o) sb += p;
    }
    ws[t] = sb - b;
    if (t == 31) blockBase = atomicAdd(base, sb);
  }
  __syncthreads();
  if (i < n) rp[i] = blockBase + (s - cp) + ws[t >> 5];
}

// fill CSR entries: (src, dinv[src]*dinv[dst]) into dst buckets. 2 edges/thread.
__global__ void k_fill(const int* __restrict__ ei, const float* __restrict__ dinv,
                       int* __restrict__ rp, float2* __restrict__ csr, int E) {
  int e = (blockIdx.x * blockDim.x + threadIdx.x) * 2;
  if (e >= E) return;
  int s0 = ei[e];
  int d0 = ei[E + e];
  float w0 = dinv[s0] * dinv[d0];
  int p0 = atomicAdd(&rp[d0], 1);
  if (e + 1 < E) {
    int s1 = ei[e + 1];
    int d1 = ei[E + e + 1];
    float w1 = dinv[s1] * dinv[d1];
    int p1 = atomicAdd(&rp[d1], 1);
    csr[p0] = make_float2(__int_as_float(s0), w0);
    csr[p1] = make_float2(__int_as_float(s1), w1);
  } else {
    csr[p0] = make_float2(__int_as_float(s0), w0);
  }
}

// ---------------- gather SpMM v5 (smem-staged CSR) ----------------
__global__ __launch_bounds__(256) void k_spmm(
    const int* __restrict__ rp, const int* __restrict__ cnt,
    const float2* __restrict__ csr, const float4* __restrict__ in,
    const float4* __restrict__ init, const float* __restrict__ bias,
    float4* __restrict__ out, int n) {
  __shared__ float4 se[SEG_CAP / 2];   // 20KB
  int tid = threadIdx.x;
  int r0 = blockIdx.x * 64;
  int rLast = min(r0 + 63, n - 1);
  int segStart = __ldg(&rp[r0]) - __ldg(&cnt[r0]);   // even
  int segEnd = __ldg(&rp[rLast]);
  int segLen = segEnd - segStart;
  bool useSmem = (segLen <= SEG_CAP);
  if (useSmem) {
    const float4* g4 = (const float4*)csr + (segStart >> 1);
    int nf4 = (segLen + 1) >> 1;
    for (int s = tid; s < nf4; s += 256) se[s] = __ldg(&g4[s]);
    __syncthreads();
  }
  int r = r0 + (tid >> 2);
  if (r >= n) return;
  int q = tid & 3;
  int len = __ldg(&cnt[r]);
  int start = __ldg(&rp[r]) - len;   // even
  float4 a0 = make_float4(0.f, 0.f, 0.f, 0.f);
  float4 a1 = make_float4(0.f, 0.f, 0.f, 0.f);
  if (init) a0 = init[(r << 2) + q];
  int i = 0;
  if (useSmem) {
    const float4* b4 = se + ((start - segStart) >> 1);
    for (; i + 8 <= len; i += 8) {
      int hb = i >> 1;
      float4 p0 = b4[hb + 0];
      float4 p1 = b4[hb + 1];
      float4 p2 = b4[hb + 2];
      float4 p3 = b4[hb + 3];
      float4 v0 = __ldg(&in[(__float_as_int(p0.x) << 2) + q]);
      float4 v1 = __ldg(&in[(__float_as_int(p0.z) << 2) + q]);
      float4 v2 = __ldg(&in[(__float_as_int(p1.x) << 2) + q]);
      float4 v3 = __ldg(&in[(__float_as_int(p1.z) << 2) + q]);
      float4 v4 = __ldg(&in[(__float_as_int(p2.x) << 2) + q]);
      float4 v5 = __ldg(&in[(__float_as_int(p2.z) << 2) + q]);
      float4 v6 = __ldg(&in[(__float_as_int(p3.x) << 2) + q]);
      float4 v7 = __ldg(&in[(__float_as_int(p3.z) << 2) + q]);
      a0.x += p0.y * v0.x; a0.y += p0.y * v0.y; a0.z += p0.y * v0.z; a0.w += p0.y * v0.w;
      a1.x += p0.w * v1.x; a1.y += p0.w * v1.y; a1.z += p0.w * v1.z; a1.w += p0.w * v1.w;
      a0.x += p1.y * v2.x; a0.y += p1.y * v2.y; a0.z += p1.y * v2.z; a0.w += p1.y * v2.w;
      a1.x += p1.w * v3.x; a1.y += p1.w * v3.y; a1.z += p1.w * v3.z; a1.w += p1.w * v3.w;
      a0.x += p2.y * v4.x; a0.y += p2.y * v4.y; a0.z += p2.y * v4.z; a0.w += p2.y * v4.w;
      a1.x += p2.w * v5.x; a1.y += p2.w * v5.y; a1.z += p2.w * v5.z; a1.w += p2.w * v5.w;
      a0.x += p3.y * v6.x; a0.y += p3.y * v6.y; a0.z += p3.y * v6.z; a0.w += p3.y * v6.w;
      a1.x += p3.w * v7.x; a1.y += p3.w * v7.y; a1.z += p3.w * v7.z; a1.w += p3.w * v7.w;
    }
    for (; i + 2 <= len; i += 2) {
      float4 p0 = b4[i >> 1];
      float4 v0 = __ldg(&in[(__float_as_int(p0.x) << 2) + q]);
      float4 v1 = __ldg(&in[(__float_as_int(p0.z) << 2) + q]);
      a0.x += p0.y * v0.x; a0.y += p0.y * v0.y; a0.z += p0.y * v0.z; a0.w += p0.y * v0.w;
      a1.x += p0.w * v1.x; a1.y += p0.w * v1.y; a1.z += p0.w * v1.z; a1.w += p0.w * v1.w;
    }
    if (i < len) {
      float2 e0 = ((const float2*)se)[(start - segStart) + i];
      float4 v0 = __ldg(&in[(__float_as_int(e0.x) << 2) + q]);
      a0.x += e0.y * v0.x; a0.y += e0.y * v0.y; a0.z += e0.y * v0.z; a0.w += e0.y * v0.w;
    }
  } else {
    const float4* csr4 = (const float4*)csr;
    int half = start >> 1;
    for (; i + 8 <= len; i += 8) {
      int hb = half + (i >> 1);
      float4 p0 = __ldg(&csr4[hb + 0]);
      float4 p1 = __ldg(&csr4[hb + 1]);
      float4 p2 = __ldg(&csr4[hb + 2]);
      float4 p3 = __ldg(&csr4[hb + 3]);
      float4 v0 = __ldg(&in[(__float_as_int(p0.x) << 2) + q]);
      float4 v1 = __ldg(&in[(__float_as_int(p0.z) << 2) + q]);
      float4 v2 = __ldg(&in[(__float_as_int(p1.x) << 2) + q]);
      float4 v3 = __ldg(&in[(__float_as_int(p1.z) << 2) + q]);
      float4 v4 = __ldg(&in[(__float_as_int(p2.x) << 2) + q]);
      float4 v5 = __ldg(&in[(__float_as_int(p2.z) << 2) + q]);
      float4 v6 = __ldg(&in[(__float_as_int(p3.x) << 2) + q]);
      float4 v7 = __ldg(&in[(__float_as_int(p3.z) << 2) + q]);
      a0.x += p0.y * v0.x; a0.y += p0.y * v0.y; a0.z += p0.y * v0.z; a0.w += p0.y * v0.w;
      a1.x += p0.w * v1.x; a1.y += p0.w * v1.y; a1.z += p0.w * v1.z; a1.w += p0.w * v1.w;
      a0.x += p1.y * v2.x; a0.y += p1.y * v2.y; a0.z += p1.y * v2.z; a0.w += p1.y * v2.w;
      a1.x += p1.w * v3.x; a1.y += p1.w * v3.y; a1.z += p1.w * v3.z; a1.w += p1.w * v3.w;
      a0.x += p2.y * v4.x; a0.y += p2.y * v4.y; a0.z += p2.y * v4.z; a0.w += p2.y * v4.w;
      a1.x += p2.w * v5.x; a1.y += p2.w * v5.y; a1.z += p2.w * v5.z; a1.w += p2.w * v5.w;
      a0.x += p3.y * v6.x; a0.y += p3.y * v6.y; a0.z += p3.y * v6.z; a0.w += p3.y * v6.w;
      a1.x += p3.w * v7.x; a1.y += p3.w * v7.y; a1.z += p3.w * v7.z; a1.w += p3.w * v7.w;
    }
    for (; i + 2 <= len; i += 2) {
      float4 p0 = __ldg(&csr4[half + (i >> 1)]);
      float4 v0 = __ldg(&in[(__float_as_int(p0.x) << 2) + q]);
      float4 v1 = __ldg(&in[(__float_as_int(p0.z) << 2) + q]);
      a0.x += p0.y * v0.x; a0.y += p0.y * v0.y; a0.z += p0.y * v0.z; a0.w += p0.y * v0.w;
      a1.x += p0.w * v1.x; a1.y += p0.w * v1.y; a1.z += p0.w * v1.z; a1.w += p0.w * v1.w;
    }
    if (i < len) {
      float2 e0 = __ldg(&csr[start + i]);
      float4 v0 = __ldg(&in[(__float_as_int(e0.x) << 2) + q]);
      a0.x += e0.y * v0.x; a0.y += e0.y * v0.y; a0.z += e0.y * v0.z; a0.w += e0.y * v0.w;
    }
  }
  float4 acc = make_float4(a0.x + a1.x, a0.y + a1.y, a0.z + a1.z, a0.w + a1.w);
  if (bias) {
    float4 bb = ((const float4*)bias)[q];
    acc = make_float4(fmaxf(acc.x + bb.x, 0.f), fmaxf(acc.y + bb.y, 0.f),
                      fmaxf(acc.z + bb.z, 0.f), fmaxf(acc.w + bb.w, 0.f));
  }
  out[(r << 2) + q] = acc;
}

// ---------------- GEMM1 (tf32 WMMA v5, double-buffered X) ----------------
// 256 thr = 8 warps (4 row-groups x 2 col-halves). X chunks double-buffered:
// gmem loads for chunk ch+1 issue before chunk ch's mma; one barrier per chunk.
__global__ __launch_bounds__(256) void k_gemm1(
    const float* __restrict__ x, const float* __restrict__ Wt,
    const float* __restrict__ invrs, float* __restrict__ y, int n) {
  __shared__ float Ws[128][68];
  __shared__ float Xs[2][64][36];
  int tid = threadIdx.x;
  int wid = tid >> 5;
  int rg = wid >> 1;
  int cg = wid & 1;
  int rowBase = blockIdx.x * 64;

  const float4* Wt4 = (const float4*)Wt;
  for (int s = tid; s < 2048; s += 256) {
    int d = s >> 4, c4 = s & 15;
    *(float4*)&Ws[d][c4 << 2] = Wt4[s];
  }

  // fixed staging slots: rows r0 and r0+32, float4-index d4
  int r0 = tid >> 3, d4 = tid & 7;
  int row0 = rowBase + r0, row1 = rowBase + r0 + 32;
  float sc0 = (row0 < n) ? __ldg(&invrs[row0]) : 0.f;
  float sc1 = (row1 < n) ? __ldg(&invrs[row1]) : 0.f;
  const float4* x4 = (const float4*)x;

  // preload chunk 0
  {
    float4 a = (row0 < n) ? x4[row0 * 32 + d4] : make_float4(0.f, 0.f, 0.f, 0.f);
    float4 b = (row1 < n) ? x4[row1 * 32 + d4] : make_float4(0.f, 0.f, 0.f, 0.f);
    float* p0 = &Xs[0][r0][d4 << 2];
    p0[0] = wmma::__float_to_tf32(a.x * sc0);
    p0[1] = wmma::__float_to_tf32(a.y * sc0);
    p0[2] = wmma::__float_to_tf32(a.z * sc0);
    p0[3] = wmma::__float_to_tf32(a.w * sc0);
    float* p1 = &Xs[0][r0 + 32][d4 << 2];
    p1[0] = wmma::__float_to_tf32(b.x * sc1);
    p1[1] = wmma::__float_to_tf32(b.y * sc1);
    p1[2] = wmma::__float_to_tf32(b.z * sc1);
    p1[3] = wmma::__float_to_tf32(b.w * sc1);
  }

  wmma::fragment<wmma::accumulator, 16, 16, 8, float> acc[2];
  wmma::fill_fragment(acc[0], 0.0f);
  wmma::fill_fragment(acc[1], 0.0f);
  __syncthreads();

  for (int ch = 0; ch < 4; ch++) {
    float4 a, b;
    if (ch < 3) {
      a = (row0 < n) ? x4[row0 * 32 + ((ch + 1) << 3) + d4] : make_float4(0.f, 0.f, 0.f, 0.f);
      b = (row1 < n) ? x4[row1 * 32 + ((ch + 1) << 3) + d4] : make_float4(0.f, 0.f, 0.f, 0.f);
    }
    int cur = ch & 1;
    #pragma unroll
    for (int kk = 0; kk < 4; kk++) {
      wmma::fragment<wmma::matrix_a, 16, 16, 8, wmma::precision::tf32, wmma::row_major> af;
      wmma::load_matrix_sync(af, &Xs[cur][rg << 4][kk << 3], 36);
      #pragma unroll
      for (int nc = 0; nc < 2; nc++) {
        wmma::fragment<wmma::matrix_b, 16, 16, 8, wmma::precision::tf32, wmma::row_major> bf;
        wmma::load_matrix_sync(bf, &Ws[(ch << 5) + (kk << 3)][(cg << 5) + (nc << 4)], 68);
        wmma::mma_sync(acc[nc], af, bf, acc[nc]);
      }
    }
    if (ch < 3) {
      float* p0 = &Xs[cur ^ 1][r0][d4 << 2];
      p0[0] = wmma::__float_to_tf32(a.x * sc0);
      p0[1] = wmma::__float_to_tf32(a.y * sc0);
      p0[2] = wmma::__float_to_tf32(a.z * sc0);
      p0[3] = wmma::__float_to_tf32(a.w * sc0);
      float* p1 = &Xs[cur ^ 1][r0 + 32][d4 << 2];
      p1[0] = wmma::__float_to_tf32(b.x * sc1);
      p1[1] = wmma::__float_to_tf32(b.y * sc1);
      p1[2] = wmma::__float_to_tf32(b.z * sc1);
      p1[3] = wmma::__float_to_tf32(b.w * sc1);
    }
    __syncthreads();
  }

  if (rowBase + 64 <= n) {
    #pragma unroll
    for (int nc = 0; nc < 2; nc++) {
      int k = (cg << 1) | nc;
      wmma::store_matrix_sync(&y[(k * n + rowBase + (rg << 4)) * 16], acc[nc], 16,
                              wmma::mem_row_major);
    }
  } else {
    float* stg = (float*)Ws;
    wmma::store_matrix_sync(&stg[(rg << 4) * 68 + (cg << 5)], acc[0], 68, wmma::mem_row_major);
    wmma::store_matrix_sync(&stg[(rg << 4) * 68 + (cg << 5) + 16], acc[1], 68, wmma::mem_row_major);
    __syncthreads();
    int r = tid >> 2;
    int ks = tid & 3;
    int row = rowBase + r;
    if (row < n) {
      float* src = &stg[r * 68 + (ks << 4)];
      float* dst = &y[(ks * n + row) * 16];
      #pragma unroll
      for (int c4 = 0; c4 < 4; c4++) *(float4*)&dst[c4 << 2] = *(float4*)&src[c4 << 2];
    }
  }
}

// ---------------- GEMM2 + cleanup ----------------
__global__ __launch_bounds__(256) void k_gemm2(
    const float* __restrict__ G, const float* __restrict__ W2,
    const float* __restrict__ b2, float* __restrict__ out,
    int* __restrict__ cnt, int* __restrict__ base, int n) {
  {
    int i = blockIdx.x * blockDim.x + threadIdx.x;
    if (i < n) cnt[i] = 0;
    if (i == 0) *base = 0;
  }
  __shared__ float Ws[64][64];
  __shared__ float Gs[64][36];
  int tid = threadIdx.x;
  int rowBase = blockIdx.x * 64;
  for (int s = tid; s < 4096; s += 256) ((float*)Ws)[s] = W2[s];
  float4 acc[4];
  #pragma unroll
  for (int i = 0; i < 4; i++) acc[i] = make_float4(0.f, 0.f, 0.f, 0.f);
  int cg = tid & 15, rg = tid >> 4;
  for (int ch = 0; ch < 2; ch++) {
    __syncthreads();
    #pragma unroll
    for (int s0 = 0; s0 < 2; s0++) {
      int s = s0 * 256 + tid;
      int kk = s >> 8, rem = s & 255;
      int r = rem >> 2, f4 = rem & 3;
      int row = rowBase + r;
      float4 vv = make_float4(0.f, 0.f, 0.f, 0.f);
      if (row < n) vv = *(const float4*)&G[(((ch << 1) | kk) * n + row) * 16 + (f4 << 2)];
      *(float4*)&Gs[r][(kk << 4) | (f4 << 2)] = vv;
    }
    __syncthreads();
    #pragma unroll
    for (int dq = 0; dq < 8; dq++) {
      int d0 = (ch << 5) + (dq << 2);
      float4 w0 = *(const float4*)&Ws[d0 + 0][cg << 2];
      float4 w1 = *(const float4*)&Ws[d0 + 1][cg << 2];
      float4 w2 = *(const float4*)&Ws[d0 + 2][cg << 2];
      float4 w3 = *(const float4*)&Ws[d0 + 3][cg << 2];
      #pragma unroll
      for (int i = 0; i < 4; i++) {
        float4 gv = *(const float4*)&Gs[(rg << 2) + i][dq << 2];
        acc[i].x += gv.x * w0.x + gv.y * w1.x + gv.z * w2.x + gv.w * w3.x;
        acc[i].y += gv.x * w0.y + gv.y * w1.y + gv.z * w2.y + gv.w * w3.y;
        acc[i].z += gv.x * w0.z + gv.y * w1.z + gv.z * w2.z + gv.w * w3.z;
        acc[i].w += gv.x * w0.w + gv.y * w1.w + gv.z * w2.w + gv.w * w3.w;
      }
    }
  }
  float4 bb = *(const float4*)&b2[cg << 2];
  #pragma unroll
  for (int i = 0; i < 4; i++) {
    int r = rowBase + (rg << 2) + i;
    if (r < n) {
      *(float4*)&out[r * 64 + (cg << 2)] = make_float4(
          acc[i].x + bb.x, acc[i].y + bb.y, acc[i].z + bb.z, acc[i].w + bb.w);
    }
  }
}

// ---------------- launch ----------------
extern "C" void kernel_launch(void* const* d_in, const int* in_sizes, int n_in,
                              void* d_out, int out_size) {
  (void)n_in; (void)out_size;
  const float* x  = (const float*)d_in[0];
  const int*   ei = (const int*)d_in[1];
  const float* W1 = (const float*)d_in[2];
  const float* b1 = (const float*)d_in[3];
  const float* W2 = (const float*)d_in[4];
  const float* b2 = (const float*)d_in[5];
  float* out = (float*)d_out;
  int n = in_sizes[0] / 128;
  int E = in_sizes[1] / 2;

  int *cnt, *rp, *base;
  float *dinv, *invrs, *Wt, *y, *t, *u, *G;
  float2* csr;
  cudaGetSymbolAddress((void**)&cnt,   g_cnt);
  cudaGetSymbolAddress((void**)&rp,    g_rp);
  cudaGetSymbolAddress((void**)&base,  g_base);
  cudaGetSymbolAddress((void**)&dinv,  g_dinv);
  cudaGetSymbolAddress((void**)&invrs, g_invrs);
  cudaGetSymbolAddress((void**)&Wt,    g_Wt);
  cudaGetSymbolAddress((void**)&csr,   g_csr);
  cudaGetSymbolAddress((void**)&y,     g_y);
  cudaGetSymbolAddress((void**)&t,     g_t);
  cudaGetSymbolAddress((void**)&u,     g_u);
  cudaGetSymbolAddress((void**)&G,     g_G);

  const int TB = 256;
  int gE2 = (E / 2 + TB - 1) / TB;
  int gR4 = (n * 4 + TB - 1) / TB;   // 64 rows per block
  int gW  = (n * 32 + TB - 1) / TB;
  int gG  = (n + 63) / 64;
  int nb  = (n + 1023) / 1024;

  // CSR build (cnt/base zeroed by previous gemm2; zero-init on load)
  k_hist<<<gE2, TB>>>(ei, cnt, E);                // #1
  k_scan1<<<nb, 1024>>>(cnt, rp, base, dinv, n);  // #2
  k_fill<<<gE2, TB>>>(ei, dinv, rp, csr, E);      // #3
  // DIAGNOSTIC (#4 -> profiled): spmm on stale y into dead scratch t.
  // t is fully overwritten by the real spmm1 below; outputs unaffected.
  k_spmm<<<gR4, TB>>>(rp, cnt, csr, (const float4*)y,
                      nullptr, nullptr, (float4*)t, n);   // #4 -> profiled
  k_prep<<<gW + 1, TB>>>(x, invrs, W1, Wt, n, gW);        // #5
  k_gemm1<<<gG, 256>>>(x, Wt, invrs, y, n);               // #6

  // layer-1 Horner: G0 = relu(y0 + A(y1 + A(y2 + A*y3)) + b1)
  k_spmm<<<gR4, TB>>>(rp, cnt, csr, (const float4*)(y + 3 * n * 16),
                      (const float4*)(y + 2 * n * 16), nullptr, (float4*)t, n);
  k_spmm<<<gR4, TB>>>(rp, cnt, csr, (const float4*)t,
                      (const float4*)(y + 1 * n * 16), nullptr, (float4*)u, n);
  k_spmm<<<gR4, TB>>>(rp, cnt, csr, (const float4*)u,
                      (const float4*)y, b1, (float4*)G, n);

  // layer-2 hops: G[k+1] = A * G[k]
  for (int k = 0; k < 3; k++) {
    k_spmm<<<gR4, TB>>>(rp, cnt, csr, (const float4*)(G + k * n * 16),
                        nullptr, nullptr, (float4*)(G + (k + 1) * n * 16), n);
  }

  // combine + bias + cleanup for next replay
  k_gemm2<<<gG, 256>>>(G, W2, b2, out, cnt, base, n);
}

// round 17
// speedup vs baseline: 1.6255x; 1.6255x over previous
#include <cuda_runtime.h>
#include <mma.h>
#include <math.h>

using namespace nvcuda;

#define NMAX 50000
#define EMAX 800000
#define SEG_CAP 1280   // max edges staged per 32-row block (mean ~512, 33 sigma)

// ---------------- scratch (no allocation allowed) ----------------
__device__ __align__(16) int   g_cnt[NMAX];        // in-degree; re-zeroed by gemm2
__device__ __align__(16) int   g_rp[NMAX];         // CSR row ptr; fill advances it to row END
__device__ int                 g_base;             // slot counter; re-zeroed by gemm2
__device__ __align__(16) float g_dinv[NMAX];
__device__ __align__(16) float g_invrs[NMAX];
__device__ __align__(16) float g_Wt[128 * 64];     // tf32, transformed W1
__device__ __align__(16) float2 g_csr[EMAX + NMAX]; // (src bits, weight); rows even-aligned
__device__ __align__(16) float g_y[4 * NMAX * 16]; // layer-1 projections y_k
__device__ __align__(16) float g_t[NMAX * 16];
__device__ __align__(16) float g_u[NMAX * 16];
__device__ __align__(16) float g_G[4 * NMAX * 16]; // layer-2 hops

// ---------------- CSR build ----------------
__global__ void k_hist(const int* __restrict__ ei, int* __restrict__ cnt, int E) {
  int e = (blockIdx.x * blockDim.x + threadIdx.x) * 2;
  if (e >= E) return;
  atomicAdd(&cnt[ei[E + e]], 1);
  if (e + 1 < E) atomicAdd(&cnt[ei[E + e + 1]], 1);
}

// warp per row: inv_rowsum = 1 / max(sum(x_row), 1e-8)
__global__ void k_invrs(const float* __restrict__ x, float* __restrict__ invrs, int n) {
  int w = (blockIdx.x * blockDim.x + threadIdx.x) >> 5;
  int lane = threadIdx.x & 31;
  if (w >= n) return;
  const float4* x4 = (const float4*)x;
  float4 v = x4[w * 32 + lane];
  float s = v.x + v.y + v.z + v.w;
  #pragma unroll
  for (int o = 16; o; o >>= 1) s += __shfl_xor_sync(0xffffffffu, s, o);
  if (lane == 0) invrs[w] = 1.0f / fmaxf(s, 1e-8f);
}

// one-time W1 transform: Wt[d*64 + k*16+f] = tf32(W1[(k*128+d)*16+f])
__global__ void k_prepW(const float* __restrict__ W1, float* __restrict__ Wt) {
  int tid = threadIdx.x;
  for (int s = tid; s < 8192; s += 256) {
    int d = s >> 6, c = s & 63;
    Wt[s] = wmma::__float_to_tf32(W1[(((c >> 4) << 7) | d) * 16 + (c & 15)]);
  }
}

// per-1024-block exclusive scan over EVEN-PADDED lengths + atomic block base.
__global__ __launch_bounds__(1024) void k_scan1(const int* __restrict__ cnt,
                                                int* __restrict__ rp,
                                                int* __restrict__ base,
                                                float* __restrict__ dinv, int n) {
  __shared__ int ws[32];
  __shared__ int blockBase;
  int t = threadIdx.x;
  int i = blockIdx.x * 1024 + t;
  int c = (i < n) ? cnt[i] : 0;
  if (i < n) dinv[i] = (c > 0) ? rsqrtf((float)c) : 0.f;
  int cp = (c + 1) & ~1;          // even-padded allocation
  int s = cp;
  #pragma unroll
  for (int o = 1; o < 32; o <<= 1) {
    int p = __shfl_up_sync(0xffffffffu, s, o);
    if ((t & 31) >= o) s += p;
  }
  if ((t & 31) == 31) ws[t >> 5] = s;
  __syncthreads();
  if (t < 32) {
    int b = ws[t];
    int sb = b;
    #pragma unroll
    for (int o = 1; o < 32; o <<= 1) {
      int p = __shfl_up_sync(0xffffffffu, sb, o);
      if (t >= o) sb += p;
    }
    ws[t] = sb - b;
    if (t == 31) blockBase = atomicAdd(base, sb);
  }
  __syncthreads();
  if (i < n) rp[i] = blockBase + (s - cp) + ws[t >> 5];
}

// fill CSR entries: (src, dinv[src]*dinv[dst]) into dst buckets.
// 2 edges/thread, vectorized int2 edge loads (e always even -> 8B aligned).
__global__ void k_fill(const int* __restrict__ ei, const float* __restrict__ dinv,
                       int* __restrict__ rp, float2* __restrict__ csr, int E) {
  int e = (blockIdx.x * blockDim.x + threadIdx.x) * 2;
  if (e >= E) return;
  if (e + 2 <= E) {
    int2 ss = *(const int2*)&ei[e];
    int2 dd = *(const int2*)&ei[E + e];
    float w0 = dinv[ss.x] * dinv[dd.x];
    float w1 = dinv[ss.y] * dinv[dd.y];
    int p0 = atomicAdd(&rp[dd.x], 1);
    int p1 = atomicAdd(&rp[dd.y], 1);
    csr[p0] = make_float2(__int_as_float(ss.x), w0);
    csr[p1] = make_float2(__int_as_float(ss.y), w1);
  } else {
    int s0 = ei[e];
    int d0 = ei[E + e];
    float w0 = dinv[s0] * dinv[d0];
    int p0 = atomicAdd(&rp[d0], 1);
    csr[p0] = make_float2(__int_as_float(s0), w0);
  }
}

// ---------------- gather SpMM v6 (smem-staged CSR, 32-row/128-thr blocks) ----------------
// Smaller blocks double the grid (1563 blocks, ~10.6/SM) to fix the 5.28-block/SM
// wave quantization seen in the round-16 profile (occ 57%, issue 33%).
__global__ __launch_bounds__(128) void k_spmm(
    const int* __restrict__ rp, const int* __restrict__ cnt,
    const float2* __restrict__ csr, const float4* __restrict__ in,
    const float4* __restrict__ init, const float* __restrict__ bias,
    float4* __restrict__ out, int n) {
  __shared__ float4 se[SEG_CAP / 2];   // 10KB
  int tid = threadIdx.x;
  int r0 = blockIdx.x * 32;
  int rLast = min(r0 + 31, n - 1);
  int segStart = __ldg(&rp[r0]) - __ldg(&cnt[r0]);   // even
  int segEnd = __ldg(&rp[rLast]);
  int segLen = segEnd - segStart;
  bool useSmem = (segLen <= SEG_CAP);
  if (useSmem) {
    const float4* g4 = (const float4*)csr + (segStart >> 1);
    int nf4 = (segLen + 1) >> 1;
    for (int s = tid; s < nf4; s += 128) se[s] = __ldg(&g4[s]);
    __syncthreads();
  }
  int r = r0 + (tid >> 2);
  if (r >= n) return;
  int q = tid & 3;
  int len = __ldg(&cnt[r]);
  int start = __ldg(&rp[r]) - len;   // even
  float4 a0 = make_float4(0.f, 0.f, 0.f, 0.f);
  float4 a1 = make_float4(0.f, 0.f, 0.f, 0.f);
  if (init) a0 = init[(r << 2) + q];
  int i = 0;
  if (useSmem) {
    const float4* b4 = se + ((start - segStart) >> 1);
    for (; i + 8 <= len; i += 8) {
      int hb = i >> 1;
      float4 p0 = b4[hb + 0];
      float4 p1 = b4[hb + 1];
      float4 p2 = b4[hb + 2];
      float4 p3 = b4[hb + 3];
      float4 v0 = __ldg(&in[(__float_as_int(p0.x) << 2) + q]);
      float4 v1 = __ldg(&in[(__float_as_int(p0.z) << 2) + q]);
      float4 v2 = __ldg(&in[(__float_as_int(p1.x) << 2) + q]);
      float4 v3 = __ldg(&in[(__float_as_int(p1.z) << 2) + q]);
      float4 v4 = __ldg(&in[(__float_as_int(p2.x) << 2) + q]);
      float4 v5 = __ldg(&in[(__float_as_int(p2.z) << 2) + q]);
      float4 v6 = __ldg(&in[(__float_as_int(p3.x) << 2) + q]);
      float4 v7 = __ldg(&in[(__float_as_int(p3.z) << 2) + q]);
      a0.x += p0.y * v0.x; a0.y += p0.y * v0.y; a0.z += p0.y * v0.z; a0.w += p0.y * v0.w;
      a1.x += p0.w * v1.x; a1.y += p0.w * v1.y; a1.z += p0.w * v1.z; a1.w += p0.w * v1.w;
      a0.x += p1.y * v2.x; a0.y += p1.y * v2.y; a0.z += p1.y * v2.z; a0.w += p1.y * v2.w;
      a1.x += p1.w * v3.x; a1.y += p1.w * v3.y; a1.z += p1.w * v3.z; a1.w += p1.w * v3.w;
      a0.x += p2.y * v4.x; a0.y += p2.y * v4.y; a0.z += p2.y * v4.z; a0.w += p2.y * v4.w;
      a1.x += p2.w * v5.x; a1.y += p2.w * v5.y; a1.z += p2.w * v5.z; a1.w += p2.w * v5.w;
      a0.x += p3.y * v6.x; a0.y += p3.y * v6.y; a0.z += p3.y * v6.z; a0.w += p3.y * v6.w;
      a1.x += p3.w * v7.x; a1.y += p3.w * v7.y; a1.z += p3.w * v7.z; a1.w += p3.w * v7.w;
    }
    for (; i + 2 <= len; i += 2) {
      float4 p0 = b4[i >> 1];
      float4 v0 = __ldg(&in[(__float_as_int(p0.x) << 2) + q]);
      float4 v1 = __ldg(&in[(__float_as_int(p0.z) << 2) + q]);
      a0.x += p0.y * v0.x; a0.y += p0.y * v0.y; a0.z += p0.y * v0.z; a0.w += p0.y * v0.w;
      a1.x += p0.w * v1.x; a1.y += p0.w * v1.y; a1.z += p0.w * v1.z; a1.w += p0.w * v1.w;
    }
    if (i < len) {
      float2 e0 = ((const float2*)se)[(start - segStart) + i];
      float4 v0 = __ldg(&in[(__float_as_int(e0.x) << 2) + q]);
      a0.x += e0.y * v0.x; a0.y += e0.y * v0.y; a0.z += e0.y * v0.z; a0.w += e0.y * v0.w;
    }
  } else {
    const float4* csr4 = (const float4*)csr;
    int half = start >> 1;
    for (; i + 8 <= len; i += 8) {
      int hb = half + (i >> 1);
      float4 p0 = __ldg(&csr4[hb + 0]);
      float4 p1 = __ldg(&csr4[hb + 1]);
      float4 p2 = __ldg(&csr4[hb + 2]);
      float4 p3 = __ldg(&csr4[hb + 3]);
      float4 v0 = __ldg(&in[(__float_as_int(p0.x) << 2) + q]);
      float4 v1 = __ldg(&in[(__float_as_int(p0.z) << 2) + q]);
      float4 v2 = __ldg(&in[(__float_as_int(p1.x) << 2) + q]);
      float4 v3 = __ldg(&in[(__float_as_int(p1.z) << 2) + q]);
      float4 v4 = __ldg(&in[(__float_as_int(p2.x) << 2) + q]);
      float4 v5 = __ldg(&in[(__float_as_int(p2.z) << 2) + q]);
      float4 v6 = __ldg(&in[(__float_as_int(p3.x) << 2) + q]);
      float4 v7 = __ldg(&in[(__float_as_int(p3.z) << 2) + q]);
      a0.x += p0.y * v0.x; a0.y += p0.y * v0.y; a0.z += p0.y * v0.z; a0.w += p0.y * v0.w;
      a1.x += p0.w * v1.x; a1.y += p0.w * v1.y; a1.z += p0.w * v1.z; a1.w += p0.w * v1.w;
      a0.x += p1.y * v2.x; a0.y += p1.y * v2.y; a0.z += p1.y * v2.z; a0.w += p1.y * v2.w;
      a1.x += p1.w * v3.x; a1.y += p1.w * v3.y; a1.z += p1.w * v3.z; a1.w += p1.w * v3.w;
      a0.x += p2.y * v4.x; a0.y += p2.y * v4.y; a0.z += p2.y * v4.z; a0.w += p2.y * v4.w;
      a1.x += p2.w * v5.x; a1.y += p2.w * v5.y; a1.z += p2.w * v5.z; a1.w += p2.w * v5.w;
      a0.x += p3.y * v6.x; a0.y += p3.y * v6.y; a0.z += p3.y * v6.z; a0.w += p3.y * v6.w;
      a1.x += p3.w * v7.x; a1.y += p3.w * v7.y; a1.z += p3.w * v7.z; a1.w += p3.w * v7.w;
    }
    for (; i + 2 <= len; i += 2) {
      float4 p0 = __ldg(&csr4[half + (i >> 1)]);
      float4 v0 = __ldg(&in[(__float_as_int(p0.x) << 2) + q]);
      float4 v1 = __ldg(&in[(__float_as_int(p0.z) << 2) + q]);
      a0.x += p0.y * v0.x; a0.y += p0.y * v0.y; a0.z += p0.y * v0.z; a0.w += p0.y * v0.w;
      a1.x += p0.w * v1.x; a1.y += p0.w * v1.y; a1.z += p0.w * v1.z; a1.w += p0.w * v1.w;
    }
    if (i < len) {
      float2 e0 = __ldg(&csr[start + i]);
      float4 v0 = __ldg(&in[(__float_as_int(e0.x) << 2) + q]);
      a0.x += e0.y * v0.x; a0.y += e0.y * v0.y; a0.z += e0.y * v0.z; a0.w += e0.y * v0.w;
    }
  }
  float4 acc = make_float4(a0.x + a1.x, a0.y + a1.y, a0.z + a1.z, a0.w + a1.w);
  if (bias) {
    float4 bb = ((const float4*)bias)[q];
    acc = make_float4(fmaxf(acc.x + bb.x, 0.f), fmaxf(acc.y + bb.y, 0.f),
                      fmaxf(acc.z + bb.z, 0.f), fmaxf(acc.w + bb.w, 0.f));
  }
  out[(r << 2) + q] = acc;
}

// ---------------- GEMM1 (tf32 WMMA v3): y[k][n][16] = (x*invrs) @ W1[k] ----------------
__global__ __launch_bounds__(256) void k_gemm1(
    const float* __restrict__ x, const float* __restrict__ Wt,
    const float* __restrict__ invrs, float* __restrict__ y, int n) {
  __shared__ float Ws[128][68];
  __shared__ float Xs[64][36];
  int tid = threadIdx.x;
  int wid = tid >> 5;
  int rg = wid >> 1;
  int cg = wid & 1;
  int rowBase = blockIdx.x * 64;

  const float4* Wt4 = (const float4*)Wt;
  for (int s = tid; s < 2048; s += 256) {
    int d = s >> 4, c4 = s & 15;
    *(float4*)&Ws[d][c4 << 2] = Wt4[s];
  }

  wmma::fragment<wmma::accumulator, 16, 16, 8, float> acc[2];
  wmma::fill_fragment(acc[0], 0.0f);
  wmma::fill_fragment(acc[1], 0.0f);

  const float4* x4 = (const float4*)x;
  for (int ch = 0; ch < 4; ch++) {
    __syncthreads();
    for (int s = tid; s < 512; s += 256) {
      int r = s >> 3, d4 = s & 7;
      int row = rowBase + r;
      float4 vv = make_float4(0.f, 0.f, 0.f, 0.f);
      float sc = 0.f;
      if (row < n) {
        vv = x4[row * 32 + (ch << 3) + d4];
        sc = __ldg(&invrs[row]);
      }
      float* dst = &Xs[r][d4 << 2];
      dst[0] = wmma::__float_to_tf32(vv.x * sc);
      dst[1] = wmma::__float_to_tf32(vv.y * sc);
      dst[2] = wmma::__float_to_tf32(vv.z * sc);
      dst[3] = wmma::__float_to_tf32(vv.w * sc);
    }
    __syncthreads();
    #pragma unroll
    for (int kk = 0; kk < 4; kk++) {
      wmma::fragment<wmma::matrix_a, 16, 16, 8, wmma::precision::tf32, wmma::row_major> af;
      wmma::load_matrix_sync(af, &Xs[rg << 4][kk << 3], 36);
      #pragma unroll
      for (int nc = 0; nc < 2; nc++) {
        wmma::fragment<wmma::matrix_b, 16, 16, 8, wmma::precision::tf32, wmma::row_major> bf;
        wmma::load_matrix_sync(bf, &Ws[(ch << 5) + (kk << 3)][(cg << 5) + (nc << 4)], 68);
        wmma::mma_sync(acc[nc], af, bf, acc[nc]);
      }
    }
  }

  if (rowBase + 64 <= n) {
    #pragma unroll
    for (int nc = 0; nc < 2; nc++) {
      int k = (cg << 1) | nc;
      wmma::store_matrix_sync(&y[(k * n + rowBase + (rg << 4)) * 16], acc[nc], 16,
                              wmma::mem_row_major);
    }
  } else {
    __syncthreads();
    float* stg = (float*)Ws;
    wmma::store_matrix_sync(&stg[(rg << 4) * 68 + (cg << 5)], acc[0], 68, wmma::mem_row_major);
    wmma::store_matrix_sync(&stg[(rg << 4) * 68 + (cg << 5) + 16], acc[1], 68, wmma::mem_row_major);
    __syncthreads();
    int r = tid >> 2;
    int ks = tid & 3;
    int row = rowBase + r;
    if (row < n) {
      float* src = &stg[r * 68 + (ks << 4)];
      float* dst = &y[(ks * n + row) * 16];
      #pragma unroll
      for (int c4 = 0; c4 < 4; c4++) *(float4*)&dst[c4 << 2] = *(float4*)&src[c4 << 2];
    }
  }
}

// ---------------- GEMM2 + cleanup ----------------
__global__ __launch_bounds__(256) void k_gemm2(
    const float* __restrict__ G, const float* __restrict__ W2,
    const float* __restrict__ b2, float* __restrict__ out,
    int* __restrict__ cnt, int* __restrict__ base, int n) {
  {
    int i = blockIdx.x * blockDim.x + threadIdx.x;
    if (i < n) cnt[i] = 0;
    if (i == 0) *base = 0;
  }
  __shared__ float Ws[64][64];
  __shared__ float Gs[64][36];
  int tid = threadIdx.x;
  int rowBase = blockIdx.x * 64;
  for (int s = tid; s < 4096; s += 256) ((float*)Ws)[s] = W2[s];
  float4 acc[4];
  #pragma unroll
  for (int i = 0; i < 4; i++) acc[i] = make_float4(0.f, 0.f, 0.f, 0.f);
  int cg = tid & 15, rg = tid >> 4;
  for (int ch = 0; ch < 2; ch++) {
    __syncthreads();
    #pragma unroll
    for (int s0 = 0; s0 < 2; s0++) {
      int s = s0 * 256 + tid;
      int kk = s >> 8, rem = s & 255;
      int r = rem >> 2, f4 = rem & 3;
      int row = rowBase + r;
      float4 vv = make_float4(0.f, 0.f, 0.f, 0.f);
      if (row < n) vv = *(const float4*)&G[(((ch << 1) | kk) * n + row) * 16 + (f4 << 2)];
      *(float4*)&Gs[r][(kk << 4) | (f4 << 2)] = vv;
    }
    __syncthreads();
    #pragma unroll
    for (int dq = 0; dq < 8; dq++) {
      int d0 = (ch << 5) + (dq << 2);
      float4 w0 = *(const float4*)&Ws[d0 + 0][cg << 2];
      float4 w1 = *(const float4*)&Ws[d0 + 1][cg << 2];
      float4 w2 = *(const float4*)&Ws[d0 + 2][cg << 2];
      float4 w3 = *(const float4*)&Ws[d0 + 3][cg << 2];
      #pragma unroll
      for (int i = 0; i < 4; i++) {
        float4 gv = *(const float4*)&Gs[(rg << 2) + i][dq << 2];
        acc[i].x += gv.x * w0.x + gv.y * w1.x + gv.z * w2.x + gv.w * w3.x;
        acc[i].y += gv.x * w0.y + gv.y * w1.y + gv.z * w2.y + gv.w * w3.y;
        acc[i].z += gv.x * w0.z + gv.y * w1.z + gv.z * w2.z + gv.w * w3.z;
        acc[i].w += gv.x * w0.w + gv.y * w1.w + gv.z * w2.w + gv.w * w3.w;
      }
    }
  }
  float4 bb = *(const float4*)&b2[cg << 2];
  #pragma unroll
  for (int i = 0; i < 4; i++) {
    int r = rowBase + (rg << 2) + i;
    if (r < n) {
      *(float4*)&out[r * 64 + (cg << 2)] = make_float4(
          acc[i].x + bb.x, acc[i].y + bb.y, acc[i].z + bb.z, acc[i].w + bb.w);
    }
  }
}

// ---------------- launch ----------------
extern "C" void kernel_launch(void* const* d_in, const int* in_sizes, int n_in,
                              void* d_out, int out_size) {
  (void)n_in; (void)out_size;
  const float* x  = (const float*)d_in[0];
  const int*   ei = (const int*)d_in[1];
  const float* W1 = (const float*)d_in[2];
  const float* b1 = (const float*)d_in[3];
  const float* W2 = (const float*)d_in[4];
  const float* b2 = (const float*)d_in[5];
  float* out = (float*)d_out;
  int n = in_sizes[0] / 128;
  int E = in_sizes[1] / 2;

  int *cnt, *rp, *base;
  float *dinv, *invrs, *Wt, *y, *t, *u, *G;
  float2* csr;
  cudaGetSymbolAddress((void**)&cnt,   g_cnt);
  cudaGetSymbolAddress((void**)&rp,    g_rp);
  cudaGetSymbolAddress((void**)&base,  g_base);
  cudaGetSymbolAddress((void**)&dinv,  g_dinv);
  cudaGetSymbolAddress((void**)&invrs, g_invrs);
  cudaGetSymbolAddress((void**)&Wt,    g_Wt);
  cudaGetSymbolAddress((void**)&csr,   g_csr);
  cudaGetSymbolAddress((void**)&y,     g_y);
  cudaGetSymbolAddress((void**)&t,     g_t);
  cudaGetSymbolAddress((void**)&u,     g_u);
  cudaGetSymbolAddress((void**)&G,     g_G);

  const int TB = 256;
  int gE2 = (E / 2 + TB - 1) / TB;
  int gR  = (n + 31) / 32;           // spmm: 32 rows per 128-thread block
  int gW  = (n * 32 + TB - 1) / TB;
  int gG  = (n + 63) / 64;
  int nb  = (n + 1023) / 1024;

  // CSR build (cnt/base zeroed by previous gemm2; zero-init on load)
  k_hist<<<gE2, TB>>>(ei, cnt, E);                // #1
  k_scan1<<<nb, 1024>>>(cnt, rp, base, dinv, n);  // #2
  k_prepW<<<1, 256>>>(W1, Wt);                    // #3
  k_fill<<<gE2, TB>>>(ei, dinv, rp, csr, E);      // #4 -> profiled
  k_invrs<<<gW, TB>>>(x, invrs, n);               // #5
  k_gemm1<<<gG, 256>>>(x, Wt, invrs, y, n);       // #6

  // layer-1 Horner: G0 = relu(y0 + A(y1 + A(y2 + A*y3)) + b1)
  k_spmm<<<gR, 128>>>(rp, cnt, csr, (const float4*)(y + 3 * n * 16),
                      (const float4*)(y + 2 * n * 16), nullptr, (float4*)t, n);
  k_spmm<<<gR, 128>>>(rp, cnt, csr, (const float4*)t,
                      (const float4*)(y + 1 * n * 16), nullptr, (float4*)u, n);
  k_spmm<<<gR, 128>>>(rp, cnt, csr, (const float4*)u,
                      (const float4*)y, b1, (float4*)G, n);

  // layer-2 hops: G[k+1] = A * G[k]
  for (int k = 0; k < 3; k++) {
    k_spmm<<<gR, 128>>>(rp, cnt, csr, (const float4*)(G + k * n * 16),
                        nullptr, nullptr, (float4*)(G + (k + 1) * n * 16), n);
  }

  // combine + bias + cleanup for next replay
  k_gemm2<<<gG, 256>>>(G, W2, b2, out, cnt, base, n);
}